// round 5
// baseline (speedup 1.0000x reference)
#include <cuda_runtime.h>

// ---------------------------------------------------------------------------
// Micromagnetic LLG solver (RK4, 5-pt exchange laplacian, SOT, demag-z).
// Round 4: halo-fused RK4 — all 4 stages computed per grid-sync using a
// 4-wide halo in shared memory. Grid syncs: 2448 -> 614. Distributed flag
// barrier (1 L2 round trip) replaces central atomic barrier.
//
//   - 128 CTAs (one per SM, single wave), tile interior 16x32, halo 4
//   - ext region (<=24x40=960 cells) staged in SMEM as float4 (LDS.128)
//   - per-step: load halo from L2, 4 stages in SMEM (__syncthreads only),
//     store interior to L2, one grid barrier
//   - garbage propagates inward 1 ring/stage => interior exact (bit-identical
//     to the per-stage-synced version)
// ---------------------------------------------------------------------------

#define NXg 256
#define NYg 256
#define NCELL (NXg * NYg)
#define TSTEPS 256
#define NSRC 3
#define NPROBE 5
#define NSIG 2
#define RELAX_STEPS 100

#define NB 128          // CTAs (<=148 SMs, single co-resident wave)
#define NT 512          // threads per CTA; each handles up to 2 ext cells
#define IX 16           // interior tile rows (x)
#define IY 32           // interior tile cols (y)
#define TILES_Y 8       // 256/IY
#define HALO 4          // RK4 stage depth
#define EXT_X (IX + 2 * HALO)   // 24
#define EXT_Y (IY + 2 * HALO)   // 40
#define MAXC (EXT_X * EXT_Y)    // 960
#define SSTRIDE EXT_Y

__device__ float g_field[2][3 * NCELL];          // double-buffered global field
__device__ volatile unsigned int g_flags[NB];    // distributed barrier flags

__global__ void reset_flags_kernel() {
    if (threadIdx.x < NB) g_flags[threadIdx.x] = 0u;
}

struct F3 { float x, y, z; };

// Distributed grid barrier: monotonic per-CTA flags, parallel polling.
__device__ __forceinline__ void gbar(unsigned int v) {
    __syncthreads();
    if (threadIdx.x == 0) {
        __threadfence();
        g_flags[blockIdx.x] = v;
    }
    if (threadIdx.x < NB) {
        while (g_flags[threadIdx.x] < v) { }
    }
    __syncthreads();
    __threadfence();   // acquire: order subsequent field loads after the poll
}

__device__ __forceinline__ F3 torque(const F3 s, const float4* __restrict__ sb,
                                     const int4 nb, const F3 Bc,
                                     float ce, float cd, float sig,
                                     float alpha, float inv) {
    float4 nN = sb[nb.x];
    float4 nS = sb[nb.y];
    float4 nW = sb[nb.z];
    float4 nE = sb[nb.w];

    float lx = nN.x + nS.x + nW.x + nE.x - 4.0f * s.x;
    float ly = nN.y + nS.y + nW.y + nE.y - 4.0f * s.y;
    float lz = nN.z + nS.z + nW.z + nE.z - 4.0f * s.z;

    float Bx = Bc.x + ce * lx;
    float By = Bc.y + ce * ly;
    float Bz = Bc.z + ce * lz + cd * s.z + sig;   // demag z only; source on z

    // m x B
    float cx = s.y * Bz - s.z * By;
    float cy = s.z * Bx - s.x * Bz;
    float cz = s.x * By - s.y * Bx;
    // m x (m x B)
    float dx = s.y * cz - s.z * cy;
    float dy = s.z * cx - s.x * cz;
    float dz = s.x * cy - s.y * cx;
    // SOT: C * m x (m x p), p=(0,1,0); m x p = (-mz, 0, mx)  (zeros exact)
    float sx = s.y * s.x;
    float sy = -(s.z * s.z + s.x * s.x);
    float sz = s.y * s.z;
    const float C_SOT = 1.0e-4f;

    F3 k;
    k.x = -inv * (cx + alpha * dx) + C_SOT * sx;
    k.y = -inv * (cy + alpha * dy) + C_SOT * sy;
    k.z = -inv * (cz + alpha * dz) + C_SOT * sz;
    return k;
}

// One full RK4 step: halo load -> 4 SMEM stages -> interior store -> barrier.
__device__ __forceinline__ void rk4_once(
    F3 mB[2], const int cs[2], const int4 nb[2], const int ig[2],
    const bool act[2], const bool inter[2], const F3 Bc[2], const float sig[2],
    float alpha, float inv, float ce, float cd, float h, float h6,
    int& cur, float4 (*sbuf)[MAXC], unsigned int& bv)
{
    F3 s[2], acc[2];
    const float* __restrict__ f0 = g_field[cur];
#pragma unroll
    for (int j = 0; j < 2; ++j) {
        F3 v;
        if (inter[j]) {
            v = mB[j];                         // own interior: register-resident
        } else {
            v.x = __ldcg(f0 + ig[j]);
            v.y = __ldcg(f0 + NCELL + ig[j]);
            v.z = __ldcg(f0 + 2 * NCELL + ig[j]);
        }
        mB[j] = v; s[j] = v;
        acc[j].x = acc[j].y = acc[j].z = 0.0f;
        if (act[j]) sbuf[0][cs[j]] = make_float4(v.x, v.y, v.z, 0.0f);
    }
    __syncthreads();

    int p = 0;
    const float cst[3] = {0.5f, 0.5f, 1.0f};
    const float wst[4] = {1.0f, 2.0f, 2.0f, 1.0f};
#pragma unroll
    for (int st = 0; st < 4; ++st) {
        F3 k[2];
#pragma unroll
        for (int j = 0; j < 2; ++j)
            k[j] = torque(s[j], sbuf[p], nb[j], Bc[j], ce, cd, sig[j], alpha, inv);
#pragma unroll
        for (int j = 0; j < 2; ++j) {
            acc[j].x += wst[st] * k[j].x;
            acc[j].y += wst[st] * k[j].y;
            acc[j].z += wst[st] * k[j].z;
            if (st < 3) {
                float c = cst[st] * h;
                s[j].x = mB[j].x + c * k[j].x;
                s[j].y = mB[j].y + c * k[j].y;
                s[j].z = mB[j].z + c * k[j].z;
                if (act[j]) sbuf[p ^ 1][cs[j]] = make_float4(s[j].x, s[j].y, s[j].z, 0.0f);
            } else {
                s[j].x = mB[j].x + h6 * acc[j].x;
                s[j].y = mB[j].y + h6 * acc[j].y;
                s[j].z = mB[j].z + h6 * acc[j].z;
            }
        }
        if (st < 3) { p ^= 1; __syncthreads(); }
    }

    float* __restrict__ w0 = g_field[cur ^ 1];
#pragma unroll
    for (int j = 0; j < 2; ++j) {
        if (inter[j]) {
            mB[j] = s[j];
            __stcg(w0 + ig[j],             s[j].x);
            __stcg(w0 + NCELL + ig[j],     s[j].y);
            __stcg(w0 + 2 * NCELL + ig[j], s[j].z);
        }
    }
    cur ^= 1;
    gbar(++bv);
}

__global__ void __launch_bounds__(NT, 1)
mm_solver_kernel(const float* __restrict__ sigarr,   // [NSIG, TSTEPS, NSRC]
                 const float* __restrict__ Bext,     // [1,3,NX,NY]
                 const float* __restrict__ msat,     // scalar
                 const int*   __restrict__ srcp,     // [NSRC,2]
                 const int*   __restrict__ probep,   // [NPROBE,2]
                 const int*   __restrict__ fb,       // scalar
                 float*       __restrict__ out)      // [NSIG, TSTEPS, NPROBE]
{
    __shared__ float4 sbuf[2][MAXC];   // 30720 B

    const int tid = threadIdx.x;
    const int bid = blockIdx.x;
    const int tx = bid / TILES_Y, ty = bid - tx * TILES_Y;
    const int x0 = tx * IX, y0 = ty * IY;
    const int ex0 = max(x0 - HALO, 0), ex1 = min(x0 + IX + HALO, NXg);
    const int ey0 = max(y0 - HALO, 0), ey1 = min(y0 + IY + HALO, NYg);
    const int nxe = ex1 - ex0, nye = ey1 - ey0;
    const int ncells = nxe * nye;      // 720..960, always > NT

    const float Msat = msat[0];
    const int finalb = fb[0];
    const float ce = (float)(2.0 * 3.5e-12 / ((double)Msat * (5e-8 * 5e-8)));
    const float cd = (float)(-(1.2566370614359172e-06) * (double)Msat);
    const float h  = (float)(175950000000.0 * 5e-12);
    const float h6 = (float)((175950000000.0 * 5e-12) / 6.0);

    int cs[2]; int4 nb[2]; int ig[2];
    bool act[2], inter[2];
    int srcj[2], prj[2];
    F3 Bc[2];
#pragma unroll
    for (int j = 0; j < 2; ++j) {
        int c = tid + j * NT;
        act[j] = (c < ncells);
        int cc = act[j] ? c : 0;
        int sx = cc / nye, sy = cc - sx * nye;
        int gx = ex0 + sx, gy = ey0 + sy;
        cs[j] = sx * SSTRIDE + sy;
        // neighbor indices: physical edge clamp == smem clamp at physical
        // boundaries; interior ext-boundary clamps only feed garbage rings.
        int sxN = max(sx - 1, 0), sxS = min(sx + 1, nxe - 1);
        int syW = max(sy - 1, 0), syE = min(sy + 1, nye - 1);
        nb[j] = make_int4(sxN * SSTRIDE + sy, sxS * SSTRIDE + sy,
                          sx * SSTRIDE + syW, sx * SSTRIDE + syE);
        ig[j] = gx * NYg + gy;
        inter[j] = act[j] && gx >= x0 && gx < x0 + IX && gy >= y0 && gy < y0 + IY;
        Bc[j].x = Bext[ig[j]];
        Bc[j].y = Bext[NCELL + ig[j]];
        Bc[j].z = Bext[2 * NCELL + ig[j]];
        srcj[j] = -1; prj[j] = -1;
        if (act[j]) {
#pragma unroll
            for (int q = 0; q < NSRC; ++q)
                if (srcp[2 * q] == gx && srcp[2 * q + 1] == gy) srcj[j] = q;
            if (inter[j]) {
#pragma unroll
                for (int q = 0; q < NPROBE; ++q)
                    if (probep[2 * q] == gx && probep[2 * q + 1] == gy) prj[j] = q;
            }
        }
    }

    // ---- init: m0 = (0,1,0) everywhere ----
    F3 mB[2], mrel[2];
    int cur = 0;
    unsigned int bv = 0;
#pragma unroll
    for (int j = 0; j < 2; ++j) {
        mB[j].x = 0.0f; mB[j].y = 1.0f; mB[j].z = 0.0f;
        if (inter[j]) {
            __stcg(&g_field[0][ig[j]],             0.0f);
            __stcg(&g_field[0][NCELL + ig[j]],     1.0f);
            __stcg(&g_field[0][2 * NCELL + ig[j]], 0.0f);
        }
    }
    gbar(++bv);

    // ---- relaxation: alpha = 0.5, no source ----
    {
        const float alpha = 0.5f;
        const float inv = 1.0f / (1.0f + alpha * alpha);
        const float zsig[2] = {0.0f, 0.0f};
        for (int i = 0; i < RELAX_STEPS; ++i)
            rk4_once(mB, cs, nb, ig, act, inter, Bc, zsig,
                     alpha, inv, ce, cd, h, h6, cur, sbuf, bv);
    }
#pragma unroll
    for (int j = 0; j < 2; ++j) mrel[j] = mB[j];

    // ---- run: alpha = 0.01, driven sources ----
    const float alpha = 0.01f;
    const float inv = 1.0f / (1.0f + alpha * alpha);

    for (int si = 0; si < NSIG; ++si) {
        if (si > 0) {
            float* __restrict__ w = g_field[cur];
#pragma unroll
            for (int j = 0; j < 2; ++j) {
                if (inter[j]) {
                    mB[j] = mrel[j];
                    __stcg(w + ig[j],             mrel[j].x);
                    __stcg(w + NCELL + ig[j],     mrel[j].y);
                    __stcg(w + 2 * NCELL + ig[j], mrel[j].z);
                }
            }
            gbar(++bv);
        }
        for (int t = 0; t < TSTEPS; ++t) {
            float sig[2];
#pragma unroll
            for (int j = 0; j < 2; ++j)
                sig[j] = (srcj[j] >= 0)
                           ? __ldg(sigarr + ((si * TSTEPS + t) * NSRC + srcj[j]))
                           : 0.0f;

            rk4_once(mB, cs, nb, ig, act, inter, Bc, sig,
                     alpha, inv, ce, cd, h, h6, cur, sbuf, bv);

#pragma unroll
            for (int j = 0; j < 2; ++j) {
                if (prj[j] >= 0) {
                    float v = finalb ? (mB[j].z - mrel[j].z) * Msat : mB[j].z;
                    out[(si * TSTEPS + t) * NPROBE + prj[j]] = v;
                }
            }
        }
    }
}

extern "C" void kernel_launch(void* const* d_in, const int* in_sizes, int n_in,
                              void* d_out, int out_size) {
    const float* list_signal = (const float*)d_in[0];
    const float* B_ext       = (const float*)d_in[1];
    const float* Msat        = (const float*)d_in[2];
    const int*   src_pos     = (const int*)d_in[3];
    const int*   probe_pos   = (const int*)d_in[4];
    const int*   final_board = (const int*)d_in[5];
    float*       out         = (float*)d_out;

    reset_flags_kernel<<<1, NB>>>();
    mm_solver_kernel<<<NB, NT>>>(list_signal, B_ext, Msat, src_pos, probe_pos,
                                 final_board, out);
}

// round 7
// speedup vs baseline: 2.7648x; 2.7648x over previous
#include <cuda_runtime.h>

// ---------------------------------------------------------------------------
// Micromagnetic LLG solver (RK4, 5-pt exchange laplacian, SOT, demag-z).
// Round 5:
//   - TWO concurrent replicas (one per signal): 614 -> 357 sequential steps
//   - halo-fused RK4 (4 stages / grid sync), 32x32 interior tile, halo 4
//   - replica-local central-counter barrier (single-word poll, 1 poller/CTA)
//     -- fixes round-4's poll-traffic L2 congestion (16K pollers -> 128)
//   - float4 global field (one LDG.128 per halo cell)
// ---------------------------------------------------------------------------

#define NXg 256
#define NYg 256
#define NCELL (NXg * NYg)
#define TSTEPS 256
#define NSRC 3
#define NPROBE 5
#define RELAX_STEPS 100

#define NB 128          // total CTAs = 2 replicas x 64 tiles; 1 per SM, co-resident
#define NT 512
#define HALO 4
#define EXT 40          // 32 interior + 2*4 halo
#define MAXC (EXT * EXT)  // 1600
#define NQ 4            // cells per thread (ceil 1600/512)

// [replica][parity][cell]
__device__ float4 g_fld[2][2][NCELL];
__device__ unsigned int g_cnt[2];
__device__ volatile unsigned int g_gen[2];

__global__ void reset_kernel() {
    if (threadIdx.x < 2) {
        g_cnt[threadIdx.x] = 0u;
        g_gen[threadIdx.x] = 0u;
    }
}

// Replica-local grid barrier: 64 arrivals on one counter, one-word gen poll
// by thread 0 only (proven round-2 pattern; minimal L2 poll traffic).
__device__ __forceinline__ void gbar(int r, unsigned int v) {
    __syncthreads();
    if (threadIdx.x == 0) {
        __threadfence();
        if (atomicAdd(&g_cnt[r], 1u) == 63u) {
            g_cnt[r] = 0u;
            __threadfence();
            g_gen[r] = v;
        } else {
            while (g_gen[r] < v) { }
        }
    }
    __syncthreads();
}

__global__ void __launch_bounds__(NT, 1)
mm_solver_kernel(const float* __restrict__ sigarr,   // [2, TSTEPS, NSRC]
                 const float* __restrict__ Bext,     // [1,3,NX,NY]
                 const float* __restrict__ msat,
                 const int*   __restrict__ srcp,     // [NSRC,2]
                 const int*   __restrict__ probep,   // [NPROBE,2]
                 const int*   __restrict__ fb,
                 float*       __restrict__ out)      // [2, TSTEPS, NPROBE]
{
    __shared__ float sb[2][3][MAXC];   // 38400 B (ping-pong stage buffers)

    const int tid = threadIdx.x;
    const int r  = blockIdx.x >> 6;       // replica = signal index
    const int tb = blockIdx.x & 63;
    const int tx = tb >> 3, ty = tb & 7;
    const int x0 = tx * 32, y0 = ty * 32;

    const float Msat = msat[0];
    const int finalb = fb[0];
    const float ce = (float)(2.0 * 3.5e-12 / ((double)Msat * (5e-8 * 5e-8)));
    const float cd = (float)(-(1.2566370614359172e-06) * (double)Msat);
    const float h  = (float)(175950000000.0 * 5e-12);
    const float h6 = (float)((175950000000.0 * 5e-12) / 6.0);
    const float C_SOT = 1.0e-4f;

    // ---- per-cell static setup (logical 40x40 ext grid, stride EXT) ----
    int meta[NQ], nbN[NQ], nbS[NQ], nbW[NQ], nbE[NQ], ig[NQ];
    float Bcx[NQ], Bcy[NQ], Bcz[NQ];
    float m0x[NQ], m0y[NQ], m0z[NQ];
    float mrelz[NQ];

#pragma unroll
    for (int q = 0; q < NQ; ++q) {
        int c  = tid + q * NT;
        int cc = (c < MAXC) ? c : 0;
        int sx = cc / EXT, sy = cc % EXT;
        int gx = x0 - HALO + sx, gy = y0 - HALO + sy;
        bool valid = (c < MAXC) && gx >= 0 && gx < NXg && gy >= 0 && gy < NYg;
        bool inter = valid && gx >= x0 && gx < x0 + 32 && gy >= y0 && gy < y0 + 32;
        // clamp-to-self at physical edges (pad mode='edge') and at ext edges
        // (garbage ring, never reaches interior within 4 stages)
        nbN[q] = (sx > 0       && gx > 0      ) ? cc - EXT : cc;
        nbS[q] = (sx < EXT - 1 && gx < NXg - 1) ? cc + EXT : cc;
        nbW[q] = (sy > 0       && gy > 0      ) ? cc - 1   : cc;
        nbE[q] = (sy < EXT - 1 && gy < NYg - 1) ? cc + 1   : cc;
        int gxc = gx < 0 ? 0 : (gx > NXg - 1 ? NXg - 1 : gx);
        int gyc = gy < 0 ? 0 : (gy > NYg - 1 ? NYg - 1 : gy);
        int ign = gxc * NYg + gyc;
        ig[q] = ign;
        Bcx[q] = Bext[ign];
        Bcy[q] = Bext[NCELL + ign];
        Bcz[q] = Bext[2 * NCELL + ign];
        int sj = 0, pj = 0;
        if (valid) {
#pragma unroll
            for (int k2 = 0; k2 < NSRC; ++k2)
                if (srcp[2 * k2] == gx && srcp[2 * k2 + 1] == gy) sj = k2 + 1;
            if (inter) {
#pragma unroll
                for (int k2 = 0; k2 < NPROBE; ++k2)
                    if (probep[2 * k2] == gx && probep[2 * k2 + 1] == gy) pj = k2 + 1;
            }
        }
        meta[q] = (valid ? 1 : 0) | (inter ? 2 : 0) | (sj << 8) | (pj << 16);
        m0x[q] = 0.0f; m0y[q] = 1.0f; m0z[q] = 0.0f;
        mrelz[q] = 0.0f;
        if (inter) g_fld[r][0][ign] = make_float4(0.0f, 1.0f, 0.0f, 0.0f);
    }

    unsigned int gv = 0;
    int cur = 0;
    gbar(r, ++gv);

    float sx_[NQ], sy_[NQ], sz_[NQ], ax_[NQ], ay_[NQ], az_[NQ], sg[NQ];

    // ---- unified step loop: 100 relax + 256 run ----
#pragma unroll 1
    for (int i = 0; i < RELAX_STEPS + TSTEPS; ++i) {
        const bool run = (i >= RELAX_STEPS);
        const int  t   = i - RELAX_STEPS;
        const float alpha = run ? 0.01f : 0.5f;
        const float inv   = run ? (1.0f / (1.0f + 0.01f * 0.01f))
                                : (1.0f / (1.0f + 0.5f * 0.5f));
        const float* sgb = sigarr + (r * TSTEPS + (run ? t : 0)) * NSRC;

        // load phase: interior from regs, halo from L2 (float4)
#pragma unroll
        for (int q = 0; q < NQ; ++q) {
            int mt = meta[q];
            sg[q] = 0.0f;
            ax_[q] = ay_[q] = az_[q] = 0.0f;
            if (mt & 1) {
                float vx, vy, vz;
                if (mt & 2) { vx = m0x[q]; vy = m0y[q]; vz = m0z[q]; }
                else {
                    float4 f = __ldcg(&g_fld[r][cur][ig[q]]);
                    vx = f.x; vy = f.y; vz = f.z;
                }
                m0x[q] = vx; m0y[q] = vy; m0z[q] = vz;
                sx_[q] = vx; sy_[q] = vy; sz_[q] = vz;
                int c = tid + q * NT;
                sb[0][0][c] = vx; sb[0][1][c] = vy; sb[0][2][c] = vz;
                int sj = (mt >> 8) & 255;
                if (sj && run) sg[q] = __ldg(sgb + sj - 1);
            }
        }
        __syncthreads();

        // 4 RK4 stages entirely in shared memory
        int p = 0;
        const float cst[3] = {0.5f, 0.5f, 1.0f};
        const float wst[4] = {1.0f, 2.0f, 2.0f, 1.0f};
#pragma unroll
        for (int st = 0; st < 4; ++st) {
#pragma unroll
            for (int q = 0; q < NQ; ++q) {
                if (!(meta[q] & 1)) continue;
                int iN = nbN[q], iS = nbS[q], iW = nbW[q], iE = nbE[q];
                float aN0 = sb[p][0][iN], aS0 = sb[p][0][iS], aW0 = sb[p][0][iW], aE0 = sb[p][0][iE];
                float aN1 = sb[p][1][iN], aS1 = sb[p][1][iS], aW1 = sb[p][1][iW], aE1 = sb[p][1][iE];
                float aN2 = sb[p][2][iN], aS2 = sb[p][2][iS], aW2 = sb[p][2][iW], aE2 = sb[p][2][iE];

                float lx = aN0 + aS0 + aW0 + aE0 - 4.0f * sx_[q];
                float ly = aN1 + aS1 + aW1 + aE1 - 4.0f * sy_[q];
                float lz = aN2 + aS2 + aW2 + aE2 - 4.0f * sz_[q];

                float Bx = Bcx[q] + ce * lx;
                float By = Bcy[q] + ce * ly;
                float Bz = Bcz[q] + ce * lz + cd * sz_[q] + sg[q];

                float cx = sy_[q] * Bz - sz_[q] * By;
                float cy = sz_[q] * Bx - sx_[q] * Bz;
                float cz = sx_[q] * By - sy_[q] * Bx;
                float dx = sy_[q] * cz - sz_[q] * cy;
                float dy = sz_[q] * cx - sx_[q] * cz;
                float dz = sx_[q] * cy - sy_[q] * cx;
                float ox = sy_[q] * sx_[q];
                float oy = -(sz_[q] * sz_[q] + sx_[q] * sx_[q]);
                float oz = sy_[q] * sz_[q];

                float kx = -inv * (cx + alpha * dx) + C_SOT * ox;
                float ky = -inv * (cy + alpha * dy) + C_SOT * oy;
                float kz = -inv * (cz + alpha * dz) + C_SOT * oz;

                ax_[q] += wst[st] * kx;
                ay_[q] += wst[st] * ky;
                az_[q] += wst[st] * kz;

                if (st < 3) {
                    float cf = cst[st] * h;
                    sx_[q] = m0x[q] + cf * kx;
                    sy_[q] = m0y[q] + cf * ky;
                    sz_[q] = m0z[q] + cf * kz;
                    int c = tid + q * NT;
                    sb[p ^ 1][0][c] = sx_[q];
                    sb[p ^ 1][1][c] = sy_[q];
                    sb[p ^ 1][2][c] = sz_[q];
                } else {
                    sx_[q] = m0x[q] + h6 * ax_[q];
                    sy_[q] = m0y[q] + h6 * ay_[q];
                    sz_[q] = m0z[q] + h6 * az_[q];
                }
            }
            if (st < 3) { __syncthreads(); p ^= 1; }
        }

        // store interior, capture relaxed z, emit probes
#pragma unroll
        for (int q = 0; q < NQ; ++q) {
            int mt = meta[q];
            if (mt & 2) {
                m0x[q] = sx_[q]; m0y[q] = sy_[q]; m0z[q] = sz_[q];
                g_fld[r][cur ^ 1][ig[q]] = make_float4(sx_[q], sy_[q], sz_[q], 0.0f);
                if (i == RELAX_STEPS - 1) mrelz[q] = sz_[q];
                int pj = (mt >> 16) & 255;
                if (pj && run) {
                    float v = finalb ? (sz_[q] - mrelz[q]) * Msat : sz_[q];
                    out[(r * TSTEPS + t) * NPROBE + pj - 1] = v;
                }
            }
        }
        cur ^= 1;
        gbar(r, ++gv);
    }
}

extern "C" void kernel_launch(void* const* d_in, const int* in_sizes, int n_in,
                              void* d_out, int out_size) {
    const float* list_signal = (const float*)d_in[0];
    const float* B_ext       = (const float*)d_in[1];
    const float* Msat        = (const float*)d_in[2];
    const int*   src_pos     = (const int*)d_in[3];
    const int*   probe_pos   = (const int*)d_in[4];
    const int*   final_board = (const int*)d_in[5];
    float*       out         = (float*)d_out;

    reset_kernel<<<1, 32>>>();
    mm_solver_kernel<<<NB, NT>>>(list_signal, B_ext, Msat, src_pos, probe_pos,
                                 final_board, out);
}

// round 8
// speedup vs baseline: 3.2779x; 1.1856x over previous
#include <cuda_runtime.h>

// ---------------------------------------------------------------------------
// Micromagnetic LLG solver (RK4, 5-pt exchange laplacian, SOT, demag-z).
// Round 7:
//   - float4 shared-memory stencil: 1 LDS.128 per neighbor (was 3 LDS.32),
//     1 STS.128 per stage store (was 3 STS.32); dynamic smem 51.2 KB
//   - shrinking per-stage active set (d <= 3-st dependence cone): 6400 ->
//     4920 cell-stage computations per CTA per step, interior still bit-exact
//   - otherwise round-5 structure: 2 concurrent replicas, halo-fused RK4
//     (4 stages / grid sync), 32x32 interior + halo 4, central-counter barrier
// ---------------------------------------------------------------------------

#define NXg 256
#define NYg 256
#define NCELL (NXg * NYg)
#define TSTEPS 256
#define NSRC 3
#define NPROBE 5
#define RELAX_STEPS 100

#define NB 128          // 2 replicas x 64 tiles, 1 CTA/SM, single wave
#define NT 512
#define HALO 4
#define EXT 40          // 32 + 2*4
#define MAXC (EXT * EXT)  // 1600
#define NQ 4
#define SMEM_BYTES (2 * MAXC * (int)sizeof(float4))   // 51200

// [replica][parity][cell]
__device__ float4 g_fld[2][2][NCELL];
__device__ unsigned int g_cnt[2];
__device__ volatile unsigned int g_gen[2];

__global__ void reset_kernel() {
    if (threadIdx.x < 2) {
        g_cnt[threadIdx.x] = 0u;
        g_gen[threadIdx.x] = 0u;
    }
}

// Replica-local grid barrier: 64 arrivals on one counter, one-word gen poll
// by thread 0 only.
__device__ __forceinline__ void gbar(int r, unsigned int v) {
    __syncthreads();
    if (threadIdx.x == 0) {
        __threadfence();
        if (atomicAdd(&g_cnt[r], 1u) == 63u) {
            g_cnt[r] = 0u;
            __threadfence();
            g_gen[r] = v;
        } else {
            while (g_gen[r] < v) { }
        }
    }
    __syncthreads();
}

__global__ void __launch_bounds__(NT, 1)
mm_solver_kernel(const float* __restrict__ sigarr,   // [2, TSTEPS, NSRC]
                 const float* __restrict__ Bext,     // [1,3,NX,NY]
                 const float* __restrict__ msat,
                 const int*   __restrict__ srcp,     // [NSRC,2]
                 const int*   __restrict__ probep,   // [NPROBE,2]
                 const int*   __restrict__ fb,
                 float*       __restrict__ out)      // [2, TSTEPS, NPROBE]
{
    extern __shared__ float4 sb4[];    // [2][MAXC] ping-pong

    const int tid = threadIdx.x;
    const int r  = blockIdx.x >> 6;       // replica = signal index
    const int tb = blockIdx.x & 63;
    const int tx = tb >> 3, ty = tb & 7;
    const int x0 = tx * 32, y0 = ty * 32;

    const float Msat = msat[0];
    const int finalb = fb[0];
    const float ce = (float)(2.0 * 3.5e-12 / ((double)Msat * (5e-8 * 5e-8)));
    const float cd = (float)(-(1.2566370614359172e-06) * (double)Msat);
    const float h  = (float)(175950000000.0 * 5e-12);
    const float h6 = (float)((175950000000.0 * 5e-12) / 6.0);
    const float C_SOT = 1.0e-4f;

    // meta bits: [0:3)=lim+1 (stage st computed iff st < lim+1), bit3=valid,
    //            bit4=interior, [8:16)=src idx+1, [16:24)=probe idx+1
    int meta[NQ], nbN[NQ], nbS[NQ], nbW[NQ], nbE[NQ], ig[NQ];
    float Bcx[NQ], Bcy[NQ], Bcz[NQ];
    float m0x[NQ], m0y[NQ], m0z[NQ];
    float mrelz[NQ];

#pragma unroll
    for (int q = 0; q < NQ; ++q) {
        int c  = tid + q * NT;
        int cc = (c < MAXC) ? c : 0;
        int sx = cc / EXT, sy = cc % EXT;
        int gx = x0 - HALO + sx, gy = y0 - HALO + sy;
        bool valid = (c < MAXC) && gx >= 0 && gx < NXg && gy >= 0 && gy < NYg;
        bool inter = valid && gx >= x0 && gx < x0 + 32 && gy >= y0 && gy < y0 + 32;
        // ring distance d = max outward distance from the 32x32 interior
        int dxn = (sx < HALO) ? (HALO - sx) : (sx >= HALO + 32 ? sx - (HALO + 31) : 0);
        int dyn = (sy < HALO) ? (HALO - sy) : (sy >= HALO + 32 ? sy - (HALO + 31) : 0);
        int d = dxn > dyn ? dxn : dyn;
        int limp1 = valid ? (4 - d) : 0;           // stages computed: st < limp1
        if (limp1 < 0) limp1 = 0;
        // neighbor clamp-to-self at physical edges (pad mode='edge'); ext-edge
        // clamps only ever feed rings outside the dependence cone
        nbN[q] = (sx > 0       && gx > 0      ) ? cc - EXT : cc;
        nbS[q] = (sx < EXT - 1 && gx < NXg - 1) ? cc + EXT : cc;
        nbW[q] = (sy > 0       && gy > 0      ) ? cc - 1   : cc;
        nbE[q] = (sy < EXT - 1 && gy < NYg - 1) ? cc + 1   : cc;
        int gxc = gx < 0 ? 0 : (gx > NXg - 1 ? NXg - 1 : gx);
        int gyc = gy < 0 ? 0 : (gy > NYg - 1 ? NYg - 1 : gy);
        int ign = gxc * NYg + gyc;
        ig[q] = ign;
        Bcx[q] = Bext[ign];
        Bcy[q] = Bext[NCELL + ign];
        Bcz[q] = Bext[2 * NCELL + ign];
        int sj = 0, pj = 0;
        if (valid) {
#pragma unroll
            for (int k2 = 0; k2 < NSRC; ++k2)
                if (srcp[2 * k2] == gx && srcp[2 * k2 + 1] == gy) sj = k2 + 1;
            if (inter) {
#pragma unroll
                for (int k2 = 0; k2 < NPROBE; ++k2)
                    if (probep[2 * k2] == gx && probep[2 * k2 + 1] == gy) pj = k2 + 1;
            }
        }
        meta[q] = limp1 | (valid ? 8 : 0) | (inter ? 16 : 0) | (sj << 8) | (pj << 16);
        m0x[q] = 0.0f; m0y[q] = 1.0f; m0z[q] = 0.0f;
        mrelz[q] = 0.0f;
        if (inter) g_fld[r][0][ign] = make_float4(0.0f, 1.0f, 0.0f, 0.0f);
    }

    unsigned int gv = 0;
    int cur = 0;
    gbar(r, ++gv);

    float sx_[NQ], sy_[NQ], sz_[NQ], ax_[NQ], ay_[NQ], az_[NQ], sg[NQ];

    // ---- unified step loop: 100 relax + 256 run ----
#pragma unroll 1
    for (int i = 0; i < RELAX_STEPS + TSTEPS; ++i) {
        const bool run = (i >= RELAX_STEPS);
        const int  t   = i - RELAX_STEPS;
        const float alpha = run ? 0.01f : 0.5f;
        const float inv   = run ? (1.0f / (1.0f + 0.01f * 0.01f))
                                : (1.0f / (1.0f + 0.5f * 0.5f));
        const float* sgb = sigarr + (r * TSTEPS + (run ? t : 0)) * NSRC;

        // load phase: interior from regs, halo from L2; fill stage buffer 0
#pragma unroll
        for (int q = 0; q < NQ; ++q) {
            int mt = meta[q];
            sg[q] = 0.0f;
            ax_[q] = ay_[q] = az_[q] = 0.0f;
            if (mt & 8) {
                float vx, vy, vz;
                if (mt & 16) { vx = m0x[q]; vy = m0y[q]; vz = m0z[q]; }
                else {
                    float4 f = __ldcg(&g_fld[r][cur][ig[q]]);
                    vx = f.x; vy = f.y; vz = f.z;
                }
                m0x[q] = vx; m0y[q] = vy; m0z[q] = vz;
                sx_[q] = vx; sy_[q] = vy; sz_[q] = vz;
                sb4[tid + q * NT] = make_float4(vx, vy, vz, 0.0f);
                int sj = (mt >> 8) & 255;
                if (sj && run) sg[q] = __ldg(sgb + sj - 1);
            }
        }
        __syncthreads();

        // 4 RK4 stages in shared memory; active set shrinks by 1 ring/stage
        int p = 0;
        const float cst[3] = {0.5f, 0.5f, 1.0f};
        const float wst[4] = {1.0f, 2.0f, 2.0f, 1.0f};
#pragma unroll
        for (int st = 0; st < 4; ++st) {
            const float4* __restrict__ rb = sb4 + p * MAXC;
            float4* __restrict__ wb = sb4 + (p ^ 1) * MAXC;
#pragma unroll
            for (int q = 0; q < NQ; ++q) {
                if (st < (meta[q] & 7)) {
                    float4 nN = rb[nbN[q]];
                    float4 nS = rb[nbS[q]];
                    float4 nW = rb[nbW[q]];
                    float4 nE = rb[nbE[q]];

                    float lx = nN.x + nS.x + nW.x + nE.x - 4.0f * sx_[q];
                    float ly = nN.y + nS.y + nW.y + nE.y - 4.0f * sy_[q];
                    float lz = nN.z + nS.z + nW.z + nE.z - 4.0f * sz_[q];

                    float Bx = Bcx[q] + ce * lx;
                    float By = Bcy[q] + ce * ly;
                    float Bz = Bcz[q] + ce * lz + cd * sz_[q] + sg[q];

                    float cx = sy_[q] * Bz - sz_[q] * By;
                    float cy = sz_[q] * Bx - sx_[q] * Bz;
                    float cz = sx_[q] * By - sy_[q] * Bx;
                    float dx = sy_[q] * cz - sz_[q] * cy;
                    float dy = sz_[q] * cx - sx_[q] * cz;
                    float dz = sx_[q] * cy - sy_[q] * cx;
                    float ox = sy_[q] * sx_[q];
                    float oy = -(sz_[q] * sz_[q] + sx_[q] * sx_[q]);
                    float oz = sy_[q] * sz_[q];

                    float kx = -inv * (cx + alpha * dx) + C_SOT * ox;
                    float ky = -inv * (cy + alpha * dy) + C_SOT * oy;
                    float kz = -inv * (cz + alpha * dz) + C_SOT * oz;

                    ax_[q] += wst[st] * kx;
                    ay_[q] += wst[st] * ky;
                    az_[q] += wst[st] * kz;

                    if (st < 3) {
                        float cf = cst[st] * h;
                        sx_[q] = m0x[q] + cf * kx;
                        sy_[q] = m0y[q] + cf * ky;
                        sz_[q] = m0z[q] + cf * kz;
                        wb[tid + q * NT] = make_float4(sx_[q], sy_[q], sz_[q], 0.0f);
                    } else {
                        sx_[q] = m0x[q] + h6 * ax_[q];
                        sy_[q] = m0y[q] + h6 * ay_[q];
                        sz_[q] = m0z[q] + h6 * az_[q];
                    }
                }
            }
            if (st < 3) { __syncthreads(); p ^= 1; }
        }

        // store interior, capture relaxed z, emit probes
#pragma unroll
        for (int q = 0; q < NQ; ++q) {
            int mt = meta[q];
            if (mt & 16) {
                m0x[q] = sx_[q]; m0y[q] = sy_[q]; m0z[q] = sz_[q];
                g_fld[r][cur ^ 1][ig[q]] = make_float4(sx_[q], sy_[q], sz_[q], 0.0f);
                if (i == RELAX_STEPS - 1) mrelz[q] = sz_[q];
                int pj = (mt >> 16) & 255;
                if (pj && run) {
                    float v = finalb ? (sz_[q] - mrelz[q]) * Msat : sz_[q];
                    out[(r * TSTEPS + t) * NPROBE + pj - 1] = v;
                }
            }
        }
        cur ^= 1;
        gbar(r, ++gv);
    }
}

extern "C" void kernel_launch(void* const* d_in, const int* in_sizes, int n_in,
                              void* d_out, int out_size) {
    const float* list_signal = (const float*)d_in[0];
    const float* B_ext       = (const float*)d_in[1];
    const float* Msat        = (const float*)d_in[2];
    const int*   src_pos     = (const int*)d_in[3];
    const int*   probe_pos   = (const int*)d_in[4];
    const int*   final_board = (const int*)d_in[5];
    float*       out         = (float*)d_out;

    cudaFuncSetAttribute(mm_solver_kernel,
                         cudaFuncAttributeMaxDynamicSharedMemorySize, SMEM_BYTES);
    reset_kernel<<<1, 32>>>();
    mm_solver_kernel<<<NB, NT, SMEM_BYTES>>>(list_signal, B_ext, Msat, src_pos,
                                             probe_pos, final_board, out);
}